// round 2
// baseline (speedup 1.0000x reference)
#include <cuda_runtime.h>
#include <math.h>

#define IN_DIM 128
#define HID    64
#define HID4   16      // HID / 4 (float4 chunks)
#define NMAX   50176
#define EMAX   800256
#define ROWS_PER_BLK 16

// ---------------- device scratch (no allocations allowed) ----------------
__device__ float d_dinv[NMAX];                  // deg, then rsqrt(deg)
__device__ float d_g  [(size_t)NMAX * HID];     // (x@W1) * dinv[row]
__device__ float d_agg[(size_t)NMAX * HID];     // layer-1 aggregation
__device__ float d_g2  [NMAX];                  // z * dinv
__device__ float d_agg2[NMAX];                  // layer-2 aggregation
__device__ int   d_src[EMAX];
__device__ int   d_dst[EMAX];
__device__ int   d_flag64;

// ---------------- edge-index width detection (int64 vs int32) ------------
// int64 values < 50000 stored little-endian: every odd int32 word is 0.
__global__ void k_detect(const int* __restrict__ ei) {
    if (threadIdx.x == 0 && blockIdx.x == 0) {
        d_flag64 = (ei[1] == 0 && ei[3] == 0 && ei[5] == 0 && ei[7] == 0) ? 1 : 0;
    }
}

__global__ void k_deg_init(int N) {
    int n = blockIdx.x * blockDim.x + threadIdx.x;
    if (n < N) d_dinv[n] = 1.0f;                // self-loop weight
}

// convert indices to int32 scratch AND accumulate weighted in-degree
__global__ void k_convert_deg(const void* __restrict__ ei_raw,
                              const float* __restrict__ ew, int E) {
    int e = blockIdx.x * blockDim.x + threadIdx.x;
    if (e >= E) return;
    int s, d;
    if (d_flag64) {
        const long long* p = (const long long*)ei_raw;
        s = (int)p[e];
        d = (int)p[E + e];
    } else {
        const int* p = (const int*)ei_raw;
        s = p[e];
        d = p[E + e];
    }
    d_src[e] = s;
    d_dst[e] = d;
    atomicAdd(&d_dinv[d], ew[e]);
}

__global__ void k_rsqrt(int N) {
    int n = blockIdx.x * blockDim.x + threadIdx.x;
    if (n < N) d_dinv[n] = rsqrtf(d_dinv[n]);   // deg >= 1 always (self-loop)
}

// ---------------- layer 1 GEMM: g = (x @ W1) * dinv, agg init = g ---------
__global__ __launch_bounds__(256)
void k_gemm1(const float* __restrict__ x, const float* __restrict__ W1, int N) {
    __shared__ float4 Ws[IN_DIM * HID4];                    // 32 KB
    __shared__ float  xs[ROWS_PER_BLK * (IN_DIM + 1)];      // padded vs bank conflicts

    int tid  = threadIdx.x;
    int row0 = blockIdx.x * ROWS_PER_BLK;

    const float4* W4 = (const float4*)W1;
    #pragma unroll
    for (int i = 0; i < (IN_DIM * HID4) / 256; i++)
        Ws[tid + i * 256] = W4[tid + i * 256];

    #pragma unroll
    for (int i = 0; i < (ROWS_PER_BLK * IN_DIM) / 256; i++) {
        int idx = tid + i * 256;
        int r = idx >> 7, k = idx & 127;
        int row = row0 + r;
        xs[r * (IN_DIM + 1) + k] = (row < N) ? x[(size_t)row * IN_DIM + k] : 0.f;
    }
    __syncthreads();

    int r  = tid >> 4;      // 16 rows
    int cg = tid & 15;      // 16 float4 column groups
    float4 acc = make_float4(0.f, 0.f, 0.f, 0.f);
    #pragma unroll
    for (int k = 0; k < IN_DIM; k++) {
        float  xv = xs[r * (IN_DIM + 1) + k];
        float4 w  = Ws[k * HID4 + cg];
        acc.x = fmaf(xv, w.x, acc.x);
        acc.y = fmaf(xv, w.y, acc.y);
        acc.z = fmaf(xv, w.z, acc.z);
        acc.w = fmaf(xv, w.w, acc.w);
    }
    int row = row0 + r;
    if (row < N) {
        float di = d_dinv[row];
        acc.x *= di; acc.y *= di; acc.z *= di; acc.w *= di;
        ((float4*)d_g  )[(size_t)row * HID4 + cg] = acc;
        ((float4*)d_agg)[(size_t)row * HID4 + cg] = acc;   // self-loop term
    }
}

// ---------------- layer 1 edge scatter: agg[dst] += ew * g[src] ----------
__global__ void k_edge1(const float* __restrict__ ew, int E) {
    int idx = blockIdx.x * blockDim.x + threadIdx.x;
    if (idx >= E * HID4) return;
    int e = idx >> 4;
    int c = idx & 15;
    int s = d_src[e];
    int d = d_dst[e];
    float w = ew[e];
    float4 gv = ((const float4*)d_g)[(size_t)s * HID4 + c];
    float4* dst = ((float4*)d_agg) + (size_t)d * HID4 + c;
    asm volatile("red.global.add.v4.f32 [%0], {%1,%2,%3,%4};"
                 :: "l"(dst),
                    "f"(w * gv.x), "f"(w * gv.y), "f"(w * gv.z), "f"(w * gv.w)
                 : "memory");
}

// --------- per-node: h1 = relu(dinv*agg + b1); z = h1@W2; g2 = z*dinv ----
__global__ void k_layer2_node(const float* __restrict__ b1,
                              const float* __restrict__ W2, int N) {
    int n = blockIdx.x;
    int c = threadIdx.x;                       // 0..63
    float v = fmaf(d_dinv[n], d_agg[(size_t)n * HID + c], b1[c]);
    v = fmaxf(v, 0.f);
    float p = v * W2[c];
    #pragma unroll
    for (int off = 16; off > 0; off >>= 1)
        p += __shfl_xor_sync(0xffffffffu, p, off);
    __shared__ float ss[2];
    if ((c & 31) == 0) ss[c >> 5] = p;
    __syncthreads();
    if (c == 0) {
        float z  = ss[0] + ss[1];
        float g2 = z * d_dinv[n];
        d_g2[n]   = g2;
        d_agg2[n] = g2;                        // self-loop term
    }
}

// ---------------- layer 2 edge scatter (scalar) ---------------------------
__global__ void k_edge2(const float* __restrict__ ew, int E) {
    int e = blockIdx.x * blockDim.x + threadIdx.x;
    if (e >= E) return;
    atomicAdd(&d_agg2[d_dst[e]], ew[e] * d_g2[d_src[e]]);
}

// ---------------- output: sigmoid(dinv*agg2 + b2) -------------------------
__global__ void k_out(const float* __restrict__ b2, float* __restrict__ out, int N) {
    int n = blockIdx.x * blockDim.x + threadIdx.x;
    if (n < N) {
        float t = fmaf(d_dinv[n], d_agg2[n], b2[0]);
        out[n] = 1.0f / (1.0f + expf(-t));
    }
}

// ---------------- launcher -------------------------------------------------
extern "C" void kernel_launch(void* const* d_in, const int* in_sizes, int n_in,
                              void* d_out, int out_size) {
    const float* x  = (const float*)d_in[0];
    const void*  ei = d_in[1];
    const float* ew = (const float*)d_in[2];
    const float* W1 = (const float*)d_in[3];
    const float* b1 = (const float*)d_in[4];
    const float* W2 = (const float*)d_in[5];
    const float* b2 = (const float*)d_in[6];
    float* out = (float*)d_out;

    int N = in_sizes[0] / IN_DIM;   // 50000
    int E = in_sizes[2];            // 800000

    k_detect<<<1, 32>>>((const int*)ei);
    k_deg_init<<<(N + 255) / 256, 256>>>(N);
    k_convert_deg<<<(E + 255) / 256, 256>>>(ei, ew, E);
    k_rsqrt<<<(N + 255) / 256, 256>>>(N);
    k_gemm1<<<(N + ROWS_PER_BLK - 1) / ROWS_PER_BLK, 256>>>(x, W1, N);

    long long tot = (long long)E * HID4;
    int blocks = (int)((tot + 255) / 256);
    k_edge1<<<blocks, 256>>>(ew, E);

    k_layer2_node<<<N, 64>>>(b1, W2, N);
    k_edge2<<<(E + 255) / 256, 256>>>(ew, E);
    k_out<<<(N + 255) / 256, 256>>>(b2, out, N);
}

// round 4
// speedup vs baseline: 1.7322x; 1.7322x over previous
#include <cuda_runtime.h>
#include <math.h>

#define IN_DIM 128
#define HID    64
#define HID4   16      // HID / 4 (float4 chunks)
#define NMAX   50176
#define EMAX   800256
#define SCAN_B 256

// ---------------- device scratch (no allocations allowed) -----------------
// Self-restoring invariant: d_deg and d_cnt are zero at the START of every
// kernel_launch call. First call: zero-initialized globals. Later calls: the
// last kernel that reads each array resets it to zero.
__device__ float d_deg [NMAX];                  // weighted in-degree accumulator
__device__ int   d_cnt [NMAX];                  // in-edge count
__device__ float d_dinv[NMAX];                  // rsqrt(1 + deg)
__device__ int   d_excl[NMAX];                  // per-block exclusive scan
__device__ int   d_bsum[256];                   // block sums
__device__ int   d_boff[256];                   // scanned block sums
__device__ int   d_start[NMAX];                 // CSR row starts
__device__ int   d_cursor[NMAX];                // fill cursors
__device__ int2  d_csr[EMAX];                   // {src, ew as bits} grouped by dst
__device__ float d_g  [(size_t)NMAX * HID];     // (x@W1) * dinv[row]
__device__ float d_g2 [NMAX];                   // (h1@W2) * dinv[row]

// -------- inline edge-index width detection (int64 vs int32) --------------
// int64 values < 50000, little-endian: high words (odd int32 slots) are 0.
__device__ __forceinline__ bool is_i64(const int* ei) {
    return (ei[1] | ei[3] | ei[5] | ei[7]) == 0;
}
__device__ __forceinline__ void load_edge(const int* ei, int E, int e,
                                          bool i64, int& s, int& d) {
    if (i64) {
        const long long* p = (const long long*)ei;
        s = (int)p[e]; d = (int)p[E + e];
    } else {
        s = ei[e]; d = ei[E + e];
    }
}

// ---------------- 1. count: weighted degree + edge count -------------------
__global__ void k_count(const int* __restrict__ ei,
                        const float* __restrict__ ew, int E) {
    int e = blockIdx.x * blockDim.x + threadIdx.x;
    if (e >= E) return;
    bool i64 = is_i64(ei);
    int s, d; load_edge(ei, E, e, i64, s, d);
    (void)s;
    atomicAdd(&d_deg[d], ew[e]);
    atomicAdd(&d_cnt[d], 1);
}

// ---------------- 2. scan phase 1: per-block exclusive scan ---------------
__global__ void k_scan1(int N) {
    __shared__ int sh[SCAN_B];
    int tid = threadIdx.x;
    int n = blockIdx.x * SCAN_B + tid;
    int v = (n < N) ? d_cnt[n] : 0;
    sh[tid] = v;
    __syncthreads();
    #pragma unroll
    for (int off = 1; off < SCAN_B; off <<= 1) {
        int t = (tid >= off) ? sh[tid - off] : 0;
        __syncthreads();
        sh[tid] += t;
        __syncthreads();
    }
    int incl = sh[tid];
    if (n < N) d_excl[n] = incl - v;
    if (tid == SCAN_B - 1) d_bsum[blockIdx.x] = incl;
}

// ---------------- 3. scan phase 2: scan the block sums (NB <= 256) --------
__global__ void k_scan2(int NB) {
    __shared__ int sh[SCAN_B];
    int tid = threadIdx.x;
    int v = (tid < NB) ? d_bsum[tid] : 0;
    sh[tid] = v;
    __syncthreads();
    #pragma unroll
    for (int off = 1; off < SCAN_B; off <<= 1) {
        int t = (tid >= off) ? sh[tid - off] : 0;
        __syncthreads();
        sh[tid] += t;
        __syncthreads();
    }
    if (tid < NB) d_boff[tid] = sh[tid] - v;
}

// --------- 4. finalize: row starts, cursors, dinv; reset deg --------------
__global__ void k_scan3(int N) {
    int n = blockIdx.x * blockDim.x + threadIdx.x;
    if (n >= N) return;
    int start = d_excl[n] + d_boff[n >> 8];
    d_start[n]  = start;
    d_cursor[n] = start;
    d_dinv[n]   = rsqrtf(1.0f + d_deg[n]);   // self-loop weight 1 => deg >= 1
    d_deg[n]    = 0.0f;                       // restore for next replay
}

// ---------------- 5. fill CSR ----------------------------------------------
__global__ void k_fill(const int* __restrict__ ei,
                       const float* __restrict__ ew, int E) {
    int e = blockIdx.x * blockDim.x + threadIdx.x;
    if (e >= E) return;
    bool i64 = is_i64(ei);
    int s, d; load_edge(ei, E, e, i64, s, d);
    int slot = atomicAdd(&d_cursor[d], 1);
    d_csr[slot] = make_int2(s, __float_as_int(ew[e]));
}

// ---------------- 6. GEMM1: g = (x @ W1) * dinv ----------------------------
// 128 threads, 32 rows/block, 4 rows/thread, 16 col-groups of float4.
#define G1_ROWS 32
__global__ __launch_bounds__(128)
void k_gemm1(const float* __restrict__ x, const float* __restrict__ W1, int N) {
    __shared__ float4 Ws[IN_DIM * HID4];              // 32 KB
    __shared__ float  xs[G1_ROWS * IN_DIM];           // 16 KB (row-major)

    int tid  = threadIdx.x;
    int row0 = blockIdx.x * G1_ROWS;

    const float4* W4 = (const float4*)W1;
    #pragma unroll
    for (int i = 0; i < (IN_DIM * HID4) / 128; i++)   // 16 iters
        Ws[tid + i * 128] = W4[tid + i * 128];

    // 32 rows x 32 float4 = 1024 float4; 8 per thread, coalesced
    float4* xs4 = (float4*)xs;
    #pragma unroll
    for (int i = 0; i < 8; i++) {
        int idx = tid + i * 128;        // 0..1023
        int r   = idx >> 5;             // 0..31
        int k4  = idx & 31;
        int row = row0 + r;
        xs4[idx] = (row < N) ? ((const float4*)x)[(size_t)row * 32 + k4]
                             : make_float4(0.f, 0.f, 0.f, 0.f);
    }
    __syncthreads();

    int cg = tid & 15;                  // float4 column group
    int rg = tid >> 4;                  // 0..7 -> rows rg*4 .. rg*4+3
    float4 a0 = make_float4(0,0,0,0), a1 = a0, a2 = a0, a3 = a0;
    const float* xr = &xs[rg * 4 * IN_DIM];
    #pragma unroll 4
    for (int k = 0; k < IN_DIM; k++) {
        float4 w  = Ws[k * HID4 + cg];
        float x0 = xr[k];
        float x1 = xr[IN_DIM + k];
        float x2 = xr[2 * IN_DIM + k];
        float x3 = xr[3 * IN_DIM + k];
        a0.x = fmaf(x0, w.x, a0.x); a0.y = fmaf(x0, w.y, a0.y);
        a0.z = fmaf(x0, w.z, a0.z); a0.w = fmaf(x0, w.w, a0.w);
        a1.x = fmaf(x1, w.x, a1.x); a1.y = fmaf(x1, w.y, a1.y);
        a1.z = fmaf(x1, w.z, a1.z); a1.w = fmaf(x1, w.w, a1.w);
        a2.x = fmaf(x2, w.x, a2.x); a2.y = fmaf(x2, w.y, a2.y);
        a2.z = fmaf(x2, w.z, a2.z); a2.w = fmaf(x2, w.w, a2.w);
        a3.x = fmaf(x3, w.x, a3.x); a3.y = fmaf(x3, w.y, a3.y);
        a3.z = fmaf(x3, w.z, a3.z); a3.w = fmaf(x3, w.w, a3.w);
    }

    float4 accs[4] = {a0, a1, a2, a3};
    #pragma unroll
    for (int j = 0; j < 4; j++) {
        int row = row0 + rg * 4 + j;
        if (row < N) {
            float di = d_dinv[row];
            float4 a = accs[j];
            a.x *= di; a.y *= di; a.z *= di; a.w *= di;
            ((float4*)d_g)[(size_t)row * HID4 + cg] = a;
        }
    }
}

// --- 7. layer-1 gather + bias + ReLU + (@W2) + scale, fully fused ----------
// 16 threads per node (half-warp), thread c owns float4 column c.
__global__ __launch_bounds__(256)
void k_agg1(const float* __restrict__ b1, const float* __restrict__ W2, int N) {
    int t = blockIdx.x * blockDim.x + threadIdx.x;
    int n = t >> 4;
    int c = t & 15;
    bool valid = (n < N);
    if (!valid) n = 0;                  // keep lanes active for shfl

    int st  = d_start[n];
    int cnt = d_cnt[n];
    const float4* g4 = (const float4*)d_g;
    float4 acc = g4[(size_t)n * HID4 + c];          // self-loop term

    int j = 0;
    for (; j + 4 <= cnt; j += 4) {                   // MLP=4 gather batch
        int2 e0 = d_csr[st + j];
        int2 e1 = d_csr[st + j + 1];
        int2 e2 = d_csr[st + j + 2];
        int2 e3 = d_csr[st + j + 3];
        float4 v0 = g4[(size_t)e0.x * HID4 + c];
        float4 v1 = g4[(size_t)e1.x * HID4 + c];
        float4 v2 = g4[(size_t)e2.x * HID4 + c];
        float4 v3 = g4[(size_t)e3.x * HID4 + c];
        float w0 = __int_as_float(e0.y), w1 = __int_as_float(e1.y);
        float w2 = __int_as_float(e2.y), w3 = __int_as_float(e3.y);
        acc.x = fmaf(w0, v0.x, fmaf(w1, v1.x, fmaf(w2, v2.x, fmaf(w3, v3.x, acc.x))));
        acc.y = fmaf(w0, v0.y, fmaf(w1, v1.y, fmaf(w2, v2.y, fmaf(w3, v3.y, acc.y))));
        acc.z = fmaf(w0, v0.z, fmaf(w1, v1.z, fmaf(w2, v2.z, fmaf(w3, v3.z, acc.z))));
        acc.w = fmaf(w0, v0.w, fmaf(w1, v1.w, fmaf(w2, v2.w, fmaf(w3, v3.w, acc.w))));
    }
    for (; j < cnt; j++) {
        int2 e = d_csr[st + j];
        float4 v = g4[(size_t)e.x * HID4 + c];
        float w = __int_as_float(e.y);
        acc.x = fmaf(w, v.x, acc.x);
        acc.y = fmaf(w, v.y, acc.y);
        acc.z = fmaf(w, v.z, acc.z);
        acc.w = fmaf(w, v.w, acc.w);
    }

    float di = d_dinv[n];
    float4 bb = ((const float4*)b1)[c];
    float4 v;
    v.x = fmaxf(fmaf(di, acc.x, bb.x), 0.f);
    v.y = fmaxf(fmaf(di, acc.y, bb.y), 0.f);
    v.z = fmaxf(fmaf(di, acc.z, bb.z), 0.f);
    v.w = fmaxf(fmaf(di, acc.w, bb.w), 0.f);
    float4 w2 = ((const float4*)W2)[c];
    float p = v.x * w2.x + v.y * w2.y + v.z * w2.z + v.w * w2.w;
    p += __shfl_xor_sync(0xffffffffu, p, 8);
    p += __shfl_xor_sync(0xffffffffu, p, 4);
    p += __shfl_xor_sync(0xffffffffu, p, 2);
    p += __shfl_xor_sync(0xffffffffu, p, 1);
    if (valid && c == 0) d_g2[n] = p * di;
}

// --- 8. layer-2 gather + sigmoid + output; reset d_cnt ----------------------
__global__ void k_agg2(const float* __restrict__ b2, float* __restrict__ out, int N) {
    int warp = (blockIdx.x * blockDim.x + threadIdx.x) >> 5;
    int lane = threadIdx.x & 31;
    if (warp >= N) return;             // warp-uniform exit
    int st  = d_start[warp];
    int cnt = d_cnt[warp];
    float acc = 0.f;
    for (int j = lane; j < cnt; j += 32) {
        int2 e = d_csr[st + j];
        acc += __int_as_float(e.y) * d_g2[e.x];
    }
    #pragma unroll
    for (int off = 16; off > 0; off >>= 1)
        acc += __shfl_xor_sync(0xffffffffu, acc, off);
    if (lane == 0) {
        float t = fmaf(d_dinv[warp], acc + d_g2[warp], b2[0]);
        out[warp] = 1.0f / (1.0f + expf(-t));
        d_cnt[warp] = 0;               // restore for next replay
    }
}

// ---------------- launcher --------------------------------------------------
extern "C" void kernel_launch(void* const* d_in, const int* in_sizes, int n_in,
                              void* d_out, int out_size) {
    const float* x  = (const float*)d_in[0];
    const int*   ei = (const int*)d_in[1];
    const float* ew = (const float*)d_in[2];
    const float* W1 = (const float*)d_in[3];
    const float* b1 = (const float*)d_in[4];
    const float* W2 = (const float*)d_in[5];
    const float* b2 = (const float*)d_in[6];
    float* out = (float*)d_out;

    int N = in_sizes[0] / IN_DIM;   // 50000
    int E = in_sizes[2];            // 800000
    int NB = (N + SCAN_B - 1) / SCAN_B;

    k_count<<<(E + 255) / 256, 256>>>(ei, ew, E);
    k_scan1<<<NB, SCAN_B>>>(N);
    k_scan2<<<1, SCAN_B>>>(NB);
    k_scan3<<<(N + 255) / 256, 256>>>(N);
    k_fill<<<(E + 255) / 256, 256>>>(ei, ew, E);
    k_gemm1<<<(N + G1_ROWS - 1) / G1_ROWS, 128>>>(x, W1, N);
    k_agg1<<<(N * 16 + 255) / 256, 256>>>(b1, W2, N);
    k_agg2<<<(N * 32 + 255) / 256, 256>>>(b2, out, N);
}